// round 11
// baseline (speedup 1.0000x reference)
#include <cuda.h>
#include <cuda_runtime.h>
#include <cuda_fp16.h>
#include <cstdint>

#define M_DIM 2048
#define N_DIM 4096
#define K_DIM 4096

// ---------------- scratch (static device globals; no runtime alloc) -------
__device__ __half g_Wh[(size_t)N_DIM * K_DIM];   // transcribed weight, fp16
__device__ __half g_Xh[(size_t)M_DIM * K_DIM];   // x, fp16

// ---------------- PTX helpers ----------------------------------------------
__device__ __forceinline__ uint32_t smem_u32(const void* p) {
    uint32_t a;
    asm("{ .reg .u64 t; cvta.to.shared.u64 t, %1; cvt.u32.u64 %0, t; }" : "=r"(a) : "l"(p));
    return a;
}
#define MBAR_INIT(a, n) \
    asm volatile("mbarrier.init.shared.b64 [%0], %1;" :: "r"(a), "r"((uint32_t)(n)) : "memory")
#define MBAR_ARRIVE(a) \
    asm volatile("mbarrier.arrive.shared.b64 _, [%0];" :: "r"(a) : "memory")
#define MBAR_WAIT(a, ph) do {                                                   \
    uint32_t _m = (a); uint32_t _p = (ph); uint32_t _d;                         \
    asm volatile("{\n\t.reg .pred p;\n\t"                                       \
        "mbarrier.try_wait.parity.acquire.cta.shared::cta.b64 p, [%1], %2;\n\t" \
        "selp.b32 %0, 1, 0, p;\n\t}"                                            \
        : "=r"(_d) : "r"(_m), "r"(_p) : "memory");                              \
    if (!_d) {                                                                  \
        asm volatile("{\n\t.reg .pred P1;\n\t"                                  \
            "WL_%=:\n\t"                                                        \
            "mbarrier.try_wait.parity.acquire.cta.shared::cta.b64 P1, [%0], %1, 0x989680;\n\t" \
            "@P1 bra.uni WD_%=;\n\t"                                            \
            "bra.uni WL_%=;\n\t"                                                \
            "WD_%=:\n\t}" :: "r"(_m), "r"(_p) : "memory");                      \
    } } while (0)

__device__ __forceinline__ void cp16(uint32_t sdst, const void* gsrc) {
    asm volatile("cp.async.cg.shared.global [%0], [%1], 16;"
                 :: "r"(sdst), "l"(gsrc) : "memory");
}
#define CPASYNC_MBAR_ARRIVE_NOINC(bar) \
    asm volatile("cp.async.mbarrier.arrive.noinc.shared.b64 [%0];" :: "r"(bar) : "memory")

__device__ __forceinline__ void ldsm_x4(uint32_t (&r)[4], uint32_t addr) {
    asm volatile("ldmatrix.sync.aligned.m8n8.x4.shared.b16 {%0,%1,%2,%3}, [%4];"
        : "=r"(r[0]), "=r"(r[1]), "=r"(r[2]), "=r"(r[3]) : "r"(addr));
}
__device__ __forceinline__ void mma16816(float (&d)[4], const uint32_t (&a)[4],
                                         uint32_t b0, uint32_t b1) {
    asm volatile("mma.sync.aligned.m16n8k16.row.col.f32.f16.f16.f32 "
        "{%0,%1,%2,%3},{%4,%5,%6,%7},{%8,%9},{%0,%1,%2,%3};"
        : "+f"(d[0]), "+f"(d[1]), "+f"(d[2]), "+f"(d[3])
        : "r"(a[0]), "r"(a[1]), "r"(a[2]), "r"(a[3]), "r"(b0), "r"(b1));
}
__device__ __forceinline__ void red_f32(float* p, float v) {
    asm volatile("red.global.add.f32 [%0], %1;" :: "l"(p), "f"(v) : "memory");
}

// ---------------------------------------------------------------------------
// Tiles: 16 x 16 grid of 128x256 output tiles (256 tiles).
//   Tiles 0..147   : full-K, one per CTA, direct store epilogue.
//   Tiles 148..255 : quarter-K split (4 x 16 chunks), RED.ADD epilogue into
//                    bias-pre-initialized output (written by prep_k).
// ---------------------------------------------------------------------------
#define NQT 108                                   // quarter-split tiles

// ---------------------------------------------------------------------------
// Kernel 1: fractal transcription of W (fp16) + fp16 round of X +
//           bias pre-init of the 108 split-K output tiles.
// ---------------------------------------------------------------------------
#define NW4 ((size_t)N_DIM * K_DIM / 4)           // 4,194,304
#define NX4 ((size_t)M_DIM * K_DIM / 4)           // 2,097,152
#define NB4 ((size_t)NQT * 8192)                  // 884,736 float4 of out
#define PREP_BLOCKS ((unsigned)((NW4 + NX4 + NB4) / 256))   // 28032 exactly

__global__ void prep_k(const float* __restrict__ x, const float* __restrict__ seed,
                       const float* __restrict__ da, const float* __restrict__ db,
                       int niter, const float* __restrict__ bias,
                       float* __restrict__ out) {
    __shared__ float sa[32], sb[32];
    if (threadIdx.x < 32 && threadIdx.x < niter) {
        sa[threadIdx.x] = da[threadIdx.x];
        sb[threadIdx.x] = db[threadIdx.x];
    }
    __syncthreads();

    size_t gid = (size_t)blockIdx.x * blockDim.x + threadIdx.x;
    if (gid < NW4) {
        size_t i = gid * 4;
        float4 w = *reinterpret_cast<const float4*>(seed + i);
        #pragma unroll 20
        for (int k = 0; k < niter; k++) {
            float a = sa[k], b = sb[k];
            w.x = fmaf(b, __sinf(w.x), a * w.x);
            w.y = fmaf(b, __sinf(w.y), a * w.y);
            w.z = fmaf(b, __sinf(w.z), a * w.z);
            w.w = fmaf(b, __sinf(w.w), a * w.w);
        }
        __half2 h0 = __floats2half2_rn(w.x, w.y);
        __half2 h1 = __floats2half2_rn(w.z, w.w);
        *reinterpret_cast<uint2*>(g_Wh + i) =
            make_uint2(*(uint32_t*)&h0, *(uint32_t*)&h1);
    } else if (gid < NW4 + NX4) {
        size_t i = (gid - NW4) * 4;
        float4 v = *reinterpret_cast<const float4*>(x + i);
        __half2 h0 = __floats2half2_rn(v.x, v.y);
        __half2 h1 = __floats2half2_rn(v.z, v.w);
        *reinterpret_cast<uint2*>(g_Xh + i) =
            make_uint2(*(uint32_t*)&h0, *(uint32_t*)&h1);
    } else {
        // bias pre-init for split-K tiles 148..255 (RED.ADD lands here)
        size_t u = gid - NW4 - NX4;          // 0 .. NB4-1
        const int tt   = (int)(u >> 13);     // split tile 0..107 (8192 f4/tile)
        const int e    = (int)(u & 8191);
        const int tile = 148 + tt;
        const int tm   = (tile & 15) << 7;
        const int tn   = (tile >> 4) << 8;   // 256-wide tiles
        const int row  = tm + (e >> 6);
        const int col4 = e & 63;
        const float4 b4 = reinterpret_cast<const float4*>(bias)[tn / 4 + col4];
        reinterpret_cast<float4*>(out)[(size_t)row * (N_DIM / 4) + tn / 4 + col4] = b4;
    }
}

// ---------------------------------------------------------------------------
// Kernel 2: persistent GEMM, 148 CTAs x 288 threads.
//   CTA tile 128x256, warp tile 64x64 (R3-proven core), BK=64, 4-stage
//   cp.async pipeline. CTA bx: full tile bx, then quarter tasks
//   j = bx, bx+148, bx+296 (j<432): tile 148 + j%108, k-quarter j/108.
// ---------------------------------------------------------------------------
#define NSTAGES 4
#define BK      64
#define A_BYTES (128 * 128)                  // 16KB
#define B_BYTES (256 * 128)                  // 32KB
#define STAGE_BYTES (A_BYTES + B_BYTES)      // 48KB
#define DYN_SMEM (NSTAGES * STAGE_BYTES + 1024)
#define NCTA    148

__device__ __forceinline__ void task_decode(int bx, int tt, int& tm, int& tn,
                                            int& kb, int& nch, bool& use_red) {
    if (tt == 0) {
        const int tile = bx;                       // 0..147
        tm = (tile & 15) << 7;
        tn = (tile >> 4) << 8;
        kb = 0; nch = 64; use_red = false;
    } else {
        const int j = bx + (tt - 1) * NCTA;        // 0..431
        const int tile = 148 + (j % NQT);
        tm = (tile & 15) << 7;
        tn = (tile >> 4) << 8;
        kb = (j / NQT) * 16;                       // k-quarter
        nch = 16; use_red = true;
    }
}

__global__ void __launch_bounds__(288, 1)
gemm_k(const float* __restrict__ bias, float* __restrict__ out) {
    extern __shared__ char dsm[];
    __shared__ uint64_t bars[2 * NSTAGES];

    const uint32_t tiles_s = (smem_u32(dsm) + 1023u) & ~1023u;
    const uint32_t bar0 = smem_u32(bars);
    const int tid = threadIdx.x;
    const int wid = tid >> 5;
    const int lane = tid & 31;
    const int bx = blockIdx.x;
    const int ntask = 1 + ((bx < 432 - 2 * NCTA) ? 3 : 2);   // bx<136 -> 4 else 3

    if (tid == 0) {
        #pragma unroll
        for (int s = 0; s < NSTAGES; s++) {
            MBAR_INIT(bar0 + s * 8, 32);              // full: 32 producer lanes
            MBAR_INIT(bar0 + (NSTAGES + s) * 8, 8);   // empty: 8 MMA warps
        }
    }
    __syncthreads();

    // ===================== producer warp (8) =====================
    if (wid == 8) {
        const int kc = lane & 7;          // 16B column within 128B row
        const int rl = lane >> 3;         // row sub-offset 0..3
        int g = 0;
        for (int tt = 0; tt < ntask; tt++) {
            int tm, tn, kb, nch; bool use_red;
            task_decode(bx, tt, tm, tn, kb, nch, use_red);
            for (int t = 0; t < nch; t++, g++) {
                const int s = g & 3;
                if (g >= NSTAGES)
                    MBAR_WAIT(bar0 + (NSTAGES + s) * 8, ((g - NSTAGES) >> 2) & 1);
                const int cc = kb + t;
                const uint32_t st = tiles_s + s * STAGE_BYTES;
                const char* gA = (const char*)(g_Xh + (size_t)tm * K_DIM) + cc * 128 + kc * 16;
                const char* gB = (const char*)(g_Wh + (size_t)tn * K_DIM) + cc * 128 + kc * 16;
                #pragma unroll
                for (int i = 0; i < 32; i++) {
                    const int row = i * 4 + rl;
                    const uint32_t so = row * 128 + ((kc * 16) ^ ((row & 7) << 4));
                    cp16(st + so, gA + (size_t)row * (K_DIM * 2));
                }
                #pragma unroll
                for (int i = 0; i < 64; i++) {
                    const int row = i * 4 + rl;
                    const uint32_t so = row * 128 + ((kc * 16) ^ ((row & 7) << 4));
                    cp16(st + A_BYTES + so, gB + (size_t)row * (K_DIM * 2));
                }
                CPASYNC_MBAR_ARRIVE_NOINC(bar0 + s * 8);
            }
        }
        return;
    }

    // ===================== MMA warps (0..7), warp tile 64x64 =====
    const int wm = (wid >> 2) * 64;      // {0,64}
    const int wn = (wid & 3) * 64;       // {0,64,128,192}

    const int a_row_l = (lane & 15);
    const int a_k16   = (lane >> 4) * 16;
    const int b_row_l = (lane & 7) + ((lane >> 4) << 3);
    const int b_k16   = ((lane >> 3) & 1) * 16;

    uint32_t a_base[4], a_xor[4];
    #pragma unroll
    for (int fm = 0; fm < 4; fm++) {
        const int r = wm + fm * 16 + a_row_l;
        a_base[fm] = r * 128;
        a_xor[fm] = (r & 7) << 4;
    }
    uint32_t b_base[4], b_xor[4];
    #pragma unroll
    for (int fn = 0; fn < 4; fn++) {
        const int r = wn + fn * 16 + b_row_l;
        b_base[fn] = r * 128;
        b_xor[fn] = (r & 7) << 4;
    }

    int g = 0;
    for (int tt = 0; tt < ntask; tt++) {
        int tm, tn, kb, nch; bool use_red;
        task_decode(bx, tt, tm, tn, kb, nch, use_red);

        float acc[4][8][4];
        #pragma unroll
        for (int i = 0; i < 4; i++)
            #pragma unroll
            for (int j = 0; j < 8; j++)
                #pragma unroll
                for (int c = 0; c < 4; c++) acc[i][j][c] = 0.f;

        for (int t = 0; t < nch; t++, g++) {
            const int s = g & 3;
            MBAR_WAIT(bar0 + s * 8, (g >> 2) & 1);
            const uint32_t sa = tiles_s + s * STAGE_BYTES;
            const uint32_t sb = sa + A_BYTES;

            #pragma unroll
            for (int ks = 0; ks < 4; ks++) {
                uint32_t af[4][4], bf[4][4];
                #pragma unroll
                for (int fm = 0; fm < 4; fm++)
                    ldsm_x4(af[fm], sa + a_base[fm] + ((ks * 32 + a_k16) ^ a_xor[fm]));
                #pragma unroll
                for (int fn = 0; fn < 4; fn++)
                    ldsm_x4(bf[fn], sb + b_base[fn] + ((ks * 32 + b_k16) ^ b_xor[fn]));
                #pragma unroll
                for (int fm = 0; fm < 4; fm++)
                    #pragma unroll
                    for (int fn = 0; fn < 4; fn++) {
                        mma16816(acc[fm][2 * fn],     af[fm], bf[fn][0], bf[fn][1]);
                        mma16816(acc[fm][2 * fn + 1], af[fm], bf[fn][2], bf[fn][3]);
                    }
            }
            __syncwarp();
            if (lane == 0) MBAR_ARRIVE(bar0 + (NSTAGES + s) * 8);
        }

        // ---- epilogue ----
        const int gid4 = lane >> 2;
        const int tig  = lane & 3;
        if (!use_red) {
            #pragma unroll
            for (int fm = 0; fm < 4; fm++) {
                const int row = tm + wm + fm * 16 + gid4;
                #pragma unroll
                for (int fn = 0; fn < 8; fn++) {
                    const int col = tn + wn + fn * 8 + tig * 2;
                    const float b0 = __ldg(&bias[col]);
                    const float b1 = __ldg(&bias[col + 1]);
                    float2 v0 = make_float2(acc[fm][fn][0] + b0, acc[fm][fn][1] + b1);
                    float2 v1 = make_float2(acc[fm][fn][2] + b0, acc[fm][fn][3] + b1);
                    *reinterpret_cast<float2*>(out + (size_t)row * N_DIM + col)       = v0;
                    *reinterpret_cast<float2*>(out + (size_t)(row + 8) * N_DIM + col) = v1;
                }
            }
        } else {
            // quarter-K partial: accumulate into bias-pre-initialized region
            #pragma unroll
            for (int fm = 0; fm < 4; fm++) {
                const int row = tm + wm + fm * 16 + gid4;
                #pragma unroll
                for (int fn = 0; fn < 8; fn++) {
                    const int col = tn + wn + fn * 8 + tig * 2;
                    red_f32(out + (size_t)row * N_DIM + col,           acc[fm][fn][0]);
                    red_f32(out + (size_t)row * N_DIM + col + 1,       acc[fm][fn][1]);
                    red_f32(out + (size_t)(row + 8) * N_DIM + col,     acc[fm][fn][2]);
                    red_f32(out + (size_t)(row + 8) * N_DIM + col + 1, acc[fm][fn][3]);
                }
            }
        }
    }
}

// ---------------------------------------------------------------------------
extern "C" void kernel_launch(void* const* d_in, const int* in_sizes, int n_in,
                              void* d_out, int out_size) {
    const float* x    = (const float*)d_in[0];   // [2048, 4096]
    const float* seed = (const float*)d_in[1];   // [4096, 4096]
    const float* da   = (const float*)d_in[2];   // [20]
    const float* db   = (const float*)d_in[3];   // [20]
    const float* bias = (const float*)d_in[4];   // [4096]
    float* out = (float*)d_out;                  // [2048, 4096]
    const int niter = in_sizes[2];

    prep_k<<<PREP_BLOCKS, 256>>>(x, seed, da, db, niter, bias, out);

    cudaFuncSetAttribute(gemm_k, cudaFuncAttributeMaxDynamicSharedMemorySize, DYN_SMEM);
    gemm_k<<<NCTA, 288, DYN_SMEM>>>(bias, out);
}